// round 4
// baseline (speedup 1.0000x reference)
#include <cuda_runtime.h>

// QuantumLayer fused single-kernel:
//  z_w(x) = sum_{u,v} C[w][u][v] * p01[u] * p23[v],  features (1,cos x,sin x).
// Each block rebuilds C (shuffle-parallel, ~1us amortized) -> shared, then
// grid-strides over 512-element chunks with packed f32x2 FMA evaluation.

#define TPB   256
#define NBLK  296            // 2 * 148 SMs -> 2 blocks/SM, single wave
#define CHUNK (TPB * 2)      // elements per block-iteration
#define STRIDE (NBLK * CHUNK)

typedef unsigned long long ull;

__device__ __forceinline__ ull pk2(float lo, float hi) {
    ull r; asm("mov.b64 %0,{%1,%2};" : "=l"(r) : "f"(lo), "f"(hi)); return r;
}
__device__ __forceinline__ void upk2(ull a, float& lo, float& hi) {
    asm("mov.b64 {%0,%1},%2;" : "=f"(lo), "=f"(hi) : "l"(a));
}
__device__ __forceinline__ ull fma2(ull a, ull b, ull c) {
    ull d; asm("fma.rn.f32x2 %0,%1,%2,%3;" : "=l"(d) : "l"(a), "l"(b), "l"(c)); return d;
}
__device__ __forceinline__ ull mul2(ull a, ull b) {
    ull d; asm("mul.rn.f32x2 %0,%1,%2;" : "=l"(d) : "l"(a), "l"(b)); return d;
}

__global__ __launch_bounds__(TPB, 2)
void qlayer_fused_kernel(const float4* __restrict__ x, float4* __restrict__ out,
                         int B, const float* __restrict__ weights) {
    __shared__ float sUr[16][16], sUi[16][16];
    __shared__ float sM[256 * 4];                 // [(j*16+k)*4 + w]
    __shared__ __align__(16) ull shC[162];        // [uv][{w01, w23}]

    const int tid = threadIdx.x;

    // ---- issue first chunk's global loads (latency hides under builder) ----
    int start = blockIdx.x * CHUNK;
    int i0 = start + tid, i1 = i0 + TPB;
    float4 xv0 = make_float4(0.f, 0.f, 0.f, 0.f), xv1 = xv0;
    if (i0 < B) xv0 = x[i0];
    if (i1 < B) xv1 = x[i1];

    // ================= builder: weights -> C (per block) =================
    {
        const int i = tid & 15;                   // row (state index)
        float vr = (i == (tid >> 4)) ? 1.0f : 0.0f;
        float vi = 0.0f;
#pragma unroll
        for (int l = 0; l < 5; ++l) {
#pragma unroll
            for (int w = 0; w < 4; ++w) {
                const float phi   = __ldg(&weights[(l * 4 + w) * 3 + 0]);
                const float theta = __ldg(&weights[(l * 4 + w) * 3 + 1]);
                const float omega = __ldg(&weights[(l * 4 + w) * 3 + 2]);
                float sp, cp, sm, cm, st, ct;
                __sincosf(0.5f * (phi + omega), &sp, &cp);
                __sincosf(0.5f * (phi - omega), &sm, &cm);
                __sincosf(0.5f * theta, &st, &ct);
                const int m = 8 >> w;
                const float pr = __shfl_xor_sync(0xffffffffu, vr, m);
                const float pi = __shfl_xor_sync(0xffffffffu, vi, m);
                const bool bit = (i & m) != 0;
                const float cAr = cp * ct;
                const float cAi = bit ? sp * ct : -sp * ct;
                const float cBr = bit ? cm * st : -cm * st;
                const float cBi = -sm * st;
                const float nvr = cAr * vr - cAi * vi + cBr * pr - cBi * pi;
                const float nvi = cAr * vi + cAi * vr + cBr * pi + cBi * pr;
                vr = nvr; vi = nvi;
            }
            const int r = (l % 3) + 1;
#pragma unroll
            for (int w = 0; w < 4; ++w) {
                const int mc = 8 >> w;
                const int mt = 8 >> ((w + r) & 3);
                const float pr = __shfl_xor_sync(0xffffffffu, vr, mt);
                const float pi = __shfl_xor_sync(0xffffffffu, vi, mt);
                if (i & mc) { vr = pr; vi = pi; }
            }
        }
        sUr[i][tid >> 4] = vr;
        sUi[i][tid >> 4] = vi;
    }
    __syncthreads();

    {   // M_w[j][k] = sum_i sign_w(i) Re(conj U_ij * U_ik)
        const int j = tid >> 4, k = tid & 15;
        float m0 = 0.f, m1 = 0.f, m2 = 0.f, m3 = 0.f;
#pragma unroll
        for (int ii = 0; ii < 16; ++ii) {
            const float p = sUr[ii][j] * sUr[ii][k] + sUi[ii][j] * sUi[ii][k];
            m0 += (ii & 8) ? -p : p;
            m1 += (ii & 4) ? -p : p;
            m2 += (ii & 2) ? -p : p;
            m3 += (ii & 1) ? -p : p;
        }
        sM[tid * 4 + 0] = m0; sM[tid * 4 + 1] = m1;
        sM[tid * 4 + 2] = m2; sM[tid * 4 + 3] = m3;
    }
    __syncthreads();

    if (tid < 81) {  // project M_w onto (1, cos, sin)^{x4} basis
        const int t0 = tid / 27, t1 = (tid / 9) % 3, t2 = (tid / 3) % 3, t3 = tid % 3;
        const int tt[4] = {t0, t1, t2, t3};
        float a0 = 0.f, a1 = 0.f, a2 = 0.f, a3 = 0.f;
#pragma unroll
        for (int b = 0; b < 16; ++b) {
            int j = 0, k = 0; float sgn = 1.0f;
#pragma unroll
            for (int q = 0; q < 4; ++q) {
                const int o = (b >> q) & 1;
                const int ti = tt[q];
                int jq, kq;
                if (ti == 2) { jq = o; kq = 1 - o; }
                else { jq = o; kq = o; if (ti == 1 && o) sgn = -sgn; }
                j = (j << 1) | jq;
                k = (k << 1) | kq;
            }
            const float* m = &sM[(j * 16 + k) * 4];
            a0 += sgn * m[0]; a1 += sgn * m[1];
            a2 += sgn * m[2]; a3 += sgn * m[3];
        }
        const int u = t0 * 3 + t1, v = t2 * 3 + t3;
        shC[2 * (u * 9 + v)]     = pk2(a0 * 0.0625f, a1 * 0.0625f);
        shC[2 * (u * 9 + v) + 1] = pk2(a2 * 0.0625f, a3 * 0.0625f);
    }
    __syncthreads();

    // ================= evaluation: grid-stride over chunks =================
    const ulonglong2* __restrict__ C2 = reinterpret_cast<const ulonglong2*>(shC);
    const ull ONE = pk2(1.0f, 1.0f);

    while (start < B) {
        // features for the 2 resident elements
        ull p01[2][9], p23[2][9];
        {
            const float4 xa[2] = {xv0, xv1};
#pragma unroll
            for (int e = 0; e < 2; ++e) {
                float c0, s0, c1, s1, c2, s2, c3, s3;
                __sincosf(xa[e].x, &s0, &c0);
                __sincosf(xa[e].y, &s1, &c1);
                __sincosf(xa[e].z, &s2, &c2);
                __sincosf(xa[e].w, &s3, &c3);
                const ull c0d = pk2(c0, c0), s0d = pk2(s0, s0);
                const ull c1d = pk2(c1, c1), s1d = pk2(s1, s1);
                const ull c2d = pk2(c2, c2), s2d = pk2(s2, s2);
                const ull c3d = pk2(c3, c3), s3d = pk2(s3, s3);
                p01[e][0] = ONE; p01[e][1] = c1d; p01[e][2] = s1d;
                p01[e][3] = c0d; p01[e][4] = mul2(c0d, c1d); p01[e][5] = mul2(c0d, s1d);
                p01[e][6] = s0d; p01[e][7] = mul2(s0d, c1d); p01[e][8] = mul2(s0d, s1d);
                p23[e][0] = ONE; p23[e][1] = c3d; p23[e][2] = s3d;
                p23[e][3] = c2d; p23[e][4] = mul2(c2d, c3d); p23[e][5] = mul2(c2d, s3d);
                p23[e][6] = s2d; p23[e][7] = mul2(s2d, c3d); p23[e][8] = mul2(s2d, s3d);
            }
        }

        // prefetch next chunk's x (hides global latency under contraction)
        const int nstart = start + STRIDE;
        const int n0 = nstart + tid, n1 = n0 + TPB;
        float4 xn0 = make_float4(0.f, 0.f, 0.f, 0.f), xn1 = xn0;
        if (n0 < B) xn0 = x[n0];
        if (n1 < B) xn1 = x[n1];

        // contraction: 8 independent accumulator chains
        ull zlo[2] = {0ull, 0ull}, zhi[2] = {0ull, 0ull};
#pragma unroll
        for (int u = 0; u < 9; ++u) {
            ull a0lo[2] = {0ull, 0ull}, a1lo[2] = {0ull, 0ull};
            ull a0hi[2] = {0ull, 0ull}, a1hi[2] = {0ull, 0ull};
#pragma unroll
            for (int v = 0; v < 9; v += 2) {
                const ulonglong2 cA = C2[u * 9 + v];
#pragma unroll
                for (int e = 0; e < 2; ++e) {
                    a0lo[e] = fma2(cA.x, p23[e][v], a0lo[e]);
                    a0hi[e] = fma2(cA.y, p23[e][v], a0hi[e]);
                }
                if (v + 1 < 9) {
                    const ulonglong2 cB = C2[u * 9 + v + 1];
#pragma unroll
                    for (int e = 0; e < 2; ++e) {
                        a1lo[e] = fma2(cB.x, p23[e][v + 1], a1lo[e]);
                        a1hi[e] = fma2(cB.y, p23[e][v + 1], a1hi[e]);
                    }
                }
            }
#pragma unroll
            for (int e = 0; e < 2; ++e) {
                zlo[e] = fma2(a0lo[e], p01[e][u], zlo[e]);
                zlo[e] = fma2(a1lo[e], p01[e][u], zlo[e]);
                zhi[e] = fma2(a0hi[e], p01[e][u], zhi[e]);
                zhi[e] = fma2(a1hi[e], p01[e][u], zhi[e]);
            }
        }

        // store
        if (i0 < B) {
            float z0, z1, z2, z3;
            upk2(zlo[0], z0, z1); upk2(zhi[0], z2, z3);
            out[i0] = make_float4(z0, z1, z2, z3);
        }
        if (i1 < B) {
            float z0, z1, z2, z3;
            upk2(zlo[1], z0, z1); upk2(zhi[1], z2, z3);
            out[i1] = make_float4(z0, z1, z2, z3);
        }

        start = nstart; i0 = n0; i1 = n1;
        xv0 = xn0; xv1 = xn1;
    }
}

// ---------------------------------------------------------------------------
extern "C" void kernel_launch(void* const* d_in, const int* in_sizes, int n_in,
                              void* d_out, int out_size) {
    int bx = 0, bw = 1;
    if (n_in >= 2 && in_sizes[0] == 60) { bx = 1; bw = 0; }
    const float* x   = (const float*)d_in[bx];
    const float* wts = (const float*)d_in[bw];
    const int B = in_sizes[bx] / 4;

    qlayer_fused_kernel<<<NBLK, TPB>>>((const float4*)x, (float4*)d_out, B, wts);
}